// round 10
// baseline (speedup 1.0000x reference)
#include <cuda_runtime.h>
#include <cuda_fp16.h>
#include <mma.h>

using namespace nvcuda;

#define V    50000
#define E    800000
#define BB   2
#define FIN  64
#define FOUT 64
#define KK   4
#define NB   ((V + 1023) / 1024)   // 49 scan blocks
#define FULLM 0xffffffffu

// ---------------- device scratch (allocation-free rule: __device__ globals) ----
// fp16 state. Per vertex v: 64 uints = 128 halves;
//   uint j in [0,32): b=0, features (2j, 2j+1); j in [32,64): b=1.
__device__ unsigned g_H0[V * 64];
__device__ unsigned g_H1[V * 64];
__device__ unsigned g_H2[V * 64];
__device__ unsigned g_H3[V * 64];
__device__ unsigned g_Wh[KK * FIN * FOUT / 2];   // fp16 weights, 2 per uint
__device__ int      g_counts[V];     // zero-init; re-zeroed by scan_write
__device__ int      g_rowptr[V + 1];
__device__ int      g_cursor[V];
__device__ int      g_bsums[NB];
__device__ int2     g_edge[E];       // (col, float-bits of val)

__device__ __forceinline__ unsigned* hsel(int k) {
    switch (k) {
        case 0: return g_H0;
        case 1: return g_H1;
        case 2: return g_H2;
        default: return g_H3;
    }
}

// ---------------- 1) fused front: transpose+mirror + histogram(x4) + W->fp16 --
#define TRANS_BLOCKS ((V * 32) / 256)            // 6250
#define HIST_THREADS (E / 4)                     // 200000 (E % 4 == 0)
#define HIST_BLOCKS  ((HIST_THREADS + 255) / 256)    // 782
#define WCONV_BLOCKS ((KK * FIN * FOUT / 2) / 256)   // 32
__global__ void front_kernel(const float* __restrict__ in,
                             const float* __restrict__ wt,
                             const int* __restrict__ rows) {
    int blk = blockIdx.x;
    if (blk < TRANS_BLOCKS) {
        int idx = blk * 256 + threadIdx.x;   // over V*32 f-pairs
        int v = idx >> 5;
        int fp = idx & 31;                   // features (2fp, 2fp+1)
        float2 a = __ldg(&reinterpret_cast<const float2*>(in)[v * 32 + fp]);          // b=0
        float2 c = __ldg(&reinterpret_cast<const float2*>(in)[V * 32 + v * 32 + fp]); // b=1
        __half2 h0 = __floats2half2_rn(a.x, a.y);
        __half2 h1 = __floats2half2_rn(c.x, c.y);
        g_H0[v * 64 + fp]      = *reinterpret_cast<unsigned*>(&h0);
        g_H0[v * 64 + 32 + fp] = *reinterpret_cast<unsigned*>(&h1);
    } else if (blk < TRANS_BLOCKS + HIST_BLOCKS) {
        int t = (blk - TRANS_BLOCKS) * 256 + threadIdx.x;
        if (t < HIST_THREADS) {
            int4 rr = __ldg(&reinterpret_cast<const int4*>(rows)[t]);
            atomicAdd(&g_counts[rr.x], 1);
            atomicAdd(&g_counts[rr.y], 1);
            atomicAdd(&g_counts[rr.z], 1);
            atomicAdd(&g_counts[rr.w], 1);
        }
    } else {
        int i = (blk - TRANS_BLOCKS - HIST_BLOCKS) * 256 + threadIdx.x;  // over 8192
        __half2 h = __floats2half2_rn(wt[2 * i], wt[2 * i + 1]);
        g_Wh[i] = *reinterpret_cast<unsigned*>(&h);
    }
}

// ---------------- 2) CSR build ------------------------------------------------
__global__ void scan_reduce_kernel() {
    __shared__ int swarp[32];
    int tid = threadIdx.x;
    int i = blockIdx.x * 1024 + tid;
    int v = (i < V) ? g_counts[i] : 0;
    for (int o = 16; o > 0; o >>= 1) v += __shfl_down_sync(FULLM, v, o);
    if ((tid & 31) == 0) swarp[tid >> 5] = v;
    __syncthreads();
    if (tid < 32) {
        int s = swarp[tid];
        for (int o = 16; o > 0; o >>= 1) s += __shfl_down_sync(FULLM, s, o);
        if (tid == 0) g_bsums[blockIdx.x] = s;
    }
}

__global__ void scan_write_kernel() {
    __shared__ int s[1024];
    __shared__ int boff;
    int tid = threadIdx.x;
    if (tid == 0) {
        int run = 0;
        for (int j = 0; j < NB; j++) {
            if (j == (int)blockIdx.x) boff = run;
            run += g_bsums[j];
        }
        if (blockIdx.x == 0) g_rowptr[V] = run;   // == E
    }
    int i = blockIdx.x * 1024 + tid;
    int v = (i < V) ? g_counts[i] : 0;
    s[tid] = v;
    __syncthreads();
#pragma unroll
    for (int o = 1; o < 1024; o <<= 1) {
        int t = (tid >= o) ? s[tid - o] : 0;
        __syncthreads();
        s[tid] += t;
        __syncthreads();
    }
    if (i < V) {
        int excl = s[tid] - v + boff;
        g_rowptr[i] = excl;
        g_cursor[i] = excl;
        g_counts[i] = 0;
    }
}

// 4 edges per thread: 4 independent atomic+store chains (MLP=4)
__global__ void scatter_kernel(const float* __restrict__ vals,
                               const int* __restrict__ rows,
                               const int* __restrict__ cols) {
    int t = blockIdx.x * blockDim.x + threadIdx.x;
    if (t >= HIST_THREADS) return;
    int4   rr = __ldg(&reinterpret_cast<const int4*>(rows)[t]);
    int4   cc = __ldg(&reinterpret_cast<const int4*>(cols)[t]);
    float4 vv = __ldg(&reinterpret_cast<const float4*>(vals)[t]);
    int p0 = atomicAdd(&g_cursor[rr.x], 1);
    int p1 = atomicAdd(&g_cursor[rr.y], 1);
    int p2 = atomicAdd(&g_cursor[rr.z], 1);
    int p3 = atomicAdd(&g_cursor[rr.w], 1);
    g_edge[p0] = make_int2(cc.x, __float_as_int(vv.x));
    g_edge[p1] = make_int2(cc.y, __float_as_int(vv.y));
    g_edge[p2] = make_int2(cc.z, __float_as_int(vv.z));
    g_edge[p3] = make_int2(cc.w, __float_as_int(vv.w));
}

// ---------------- 3) CSR SpMM (edge-broadcast + shuffle, 4-way gather MLP) ----
// One warp per row. Per 32-edge window, lane l prefetches edge s+l (coalesced),
// then (col,val) come from shuffles — no memory op in the address path — and
// gathers issue 4 at a time into 4 independent accumulators.
__global__ void spmm_csr_kernel(int ksrc, int kdst, int kprev,
                                float alpha, float beta) {
    int gtid = blockIdx.x * blockDim.x + threadIdx.x;
    int r = gtid >> 5;
    int lane = gtid & 31;
    if (r >= V) return;

    const uint2* __restrict__ hx = reinterpret_cast<const uint2*>(hsel(ksrc));
    int s = g_rowptr[r];
    int e = g_rowptr[r + 1];

    float4 acc[4];
#pragma unroll
    for (int q = 0; q < 4; q++) acc[q] = make_float4(0.f, 0.f, 0.f, 0.f);

    for (int base = s; base < e; base += 32) {
        int cnt = min(32, e - base);
        int2 my = (lane < cnt) ? __ldg(&g_edge[base + lane]) : make_int2(0, 0);
        int j = 0;
        for (; j + 4 <= cnt; j += 4) {
            int   c0 = __shfl_sync(FULLM, my.x, j);
            int   c1 = __shfl_sync(FULLM, my.x, j + 1);
            int   c2 = __shfl_sync(FULLM, my.x, j + 2);
            int   c3 = __shfl_sync(FULLM, my.x, j + 3);
            float v0 = __int_as_float(__shfl_sync(FULLM, my.y, j));
            float v1 = __int_as_float(__shfl_sync(FULLM, my.y, j + 1));
            float v2 = __int_as_float(__shfl_sync(FULLM, my.y, j + 2));
            float v3 = __int_as_float(__shfl_sync(FULLM, my.y, j + 3));
            uint2 r0 = __ldg(&hx[c0 * 32 + lane]);
            uint2 r1 = __ldg(&hx[c1 * 32 + lane]);
            uint2 r2 = __ldg(&hx[c2 * 32 + lane]);
            uint2 r3 = __ldg(&hx[c3 * 32 + lane]);
            float2 a0 = __half22float2(*reinterpret_cast<__half2*>(&r0.x));
            float2 a1 = __half22float2(*reinterpret_cast<__half2*>(&r0.y));
            acc[0].x = fmaf(v0, a0.x, acc[0].x);
            acc[0].y = fmaf(v0, a0.y, acc[0].y);
            acc[0].z = fmaf(v0, a1.x, acc[0].z);
            acc[0].w = fmaf(v0, a1.y, acc[0].w);
            float2 b0 = __half22float2(*reinterpret_cast<__half2*>(&r1.x));
            float2 b1 = __half22float2(*reinterpret_cast<__half2*>(&r1.y));
            acc[1].x = fmaf(v1, b0.x, acc[1].x);
            acc[1].y = fmaf(v1, b0.y, acc[1].y);
            acc[1].z = fmaf(v1, b1.x, acc[1].z);
            acc[1].w = fmaf(v1, b1.y, acc[1].w);
            float2 d0 = __half22float2(*reinterpret_cast<__half2*>(&r2.x));
            float2 d1 = __half22float2(*reinterpret_cast<__half2*>(&r2.y));
            acc[2].x = fmaf(v2, d0.x, acc[2].x);
            acc[2].y = fmaf(v2, d0.y, acc[2].y);
            acc[2].z = fmaf(v2, d1.x, acc[2].z);
            acc[2].w = fmaf(v2, d1.y, acc[2].w);
            float2 g0 = __half22float2(*reinterpret_cast<__half2*>(&r3.x));
            float2 g1 = __half22float2(*reinterpret_cast<__half2*>(&r3.y));
            acc[3].x = fmaf(v3, g0.x, acc[3].x);
            acc[3].y = fmaf(v3, g0.y, acc[3].y);
            acc[3].z = fmaf(v3, g1.x, acc[3].z);
            acc[3].w = fmaf(v3, g1.y, acc[3].w);
        }
        for (; j < cnt; j++) {
            int   c0 = __shfl_sync(FULLM, my.x, j);
            float v0 = __int_as_float(__shfl_sync(FULLM, my.y, j));
            uint2 r0 = __ldg(&hx[c0 * 32 + lane]);
            float2 a0 = __half22float2(*reinterpret_cast<__half2*>(&r0.x));
            float2 a1 = __half22float2(*reinterpret_cast<__half2*>(&r0.y));
            acc[0].x = fmaf(v0, a0.x, acc[0].x);
            acc[0].y = fmaf(v0, a0.y, acc[0].y);
            acc[0].z = fmaf(v0, a1.x, acc[0].z);
            acc[0].w = fmaf(v0, a1.y, acc[0].w);
        }
    }
    float4 t0 = make_float4(acc[0].x + acc[1].x + acc[2].x + acc[3].x,
                            acc[0].y + acc[1].y + acc[2].y + acc[3].y,
                            acc[0].z + acc[1].z + acc[2].z + acc[3].z,
                            acc[0].w + acc[1].w + acc[2].w + acc[3].w);

    float4 o;
    if (beta != 0.f) {
        uint2 rp = __ldg(&reinterpret_cast<const uint2*>(hsel(kprev))[r * 32 + lane]);
        float2 p0 = __half22float2(*reinterpret_cast<__half2*>(&rp.x));
        float2 p1 = __half22float2(*reinterpret_cast<__half2*>(&rp.y));
        o.x = fmaf(beta, p0.x, alpha * t0.x);
        o.y = fmaf(beta, p0.y, alpha * t0.y);
        o.z = fmaf(beta, p1.x, alpha * t0.z);
        o.w = fmaf(beta, p1.y, alpha * t0.w);
    } else {
        o.x = alpha * t0.x; o.y = alpha * t0.y;
        o.z = alpha * t0.z; o.w = alpha * t0.w;
    }

    uint2 m;
    __half2 m0 = __floats2half2_rn(o.x, o.y);
    __half2 m1 = __floats2half2_rn(o.z, o.w);
    m.x = *reinterpret_cast<unsigned*>(&m0);
    m.y = *reinterpret_cast<unsigned*>(&m1);
    reinterpret_cast<uint2*>(hsel(kdst))[r * 32 + lane] = m;
}

// ---------------- 4) tensor-core GEMM ----------------------------------------
#define AP 72   // padded half stride
__global__ void gemm_kernel(const float* __restrict__ bias,
                            float* __restrict__ out) {
    __shared__ __align__(16) char sbuf[35840];
    unsigned* As_u = reinterpret_cast<unsigned*>(sbuf);            // 128*36*4
    unsigned* Bs_u = reinterpret_cast<unsigned*>(sbuf + 18432);    //  64*36*4
    float*    Cs   = reinterpret_cast<float*>(sbuf);               // epilogue

    int tid = threadIdx.x;
    int w = tid >> 5;
    int lane = tid & 31;
    int rho0 = blockIdx.x * 128;

    wmma::fragment<wmma::accumulator, 16, 16, 16, float> acc[4];
#pragma unroll
    for (int nt = 0; nt < 4; nt++) wmma::fill_fragment(acc[nt], 0.f);

    for (int k = 0; k < KK; k++) {
        __syncthreads();
        const unsigned* m = hsel(k);
#pragma unroll
        for (int it = 0; it < 16; it++) {        // A: 128 rho-rows x 32 uints
            int i = tid + it * 256;
            int r = i >> 5, cu = i & 31;
            int rho = rho0 + r;
            unsigned val = 0u;
            if (rho < 2 * V)
                val = __ldcg(&m[(rho >> 1) * 64 + (rho & 1) * 32 + cu]);
            As_u[r * 36 + cu] = val;
        }
#pragma unroll
        for (int it = 0; it < 8; it++) {         // B: 64 f-rows x 32 uints
            int i = tid + it * 256;
            int f = i >> 5, cu = i & 31;
            Bs_u[f * 36 + cu] = __ldg(&g_Wh[(f * 4 + k) * 32 + cu]);
        }
        __syncthreads();

        const __half* As = reinterpret_cast<const __half*>(As_u);
        const __half* Bs = reinterpret_cast<const __half*>(Bs_u);
#pragma unroll
        for (int kc = 0; kc < 4; kc++) {
            wmma::fragment<wmma::matrix_a, 16, 16, 16, __half, wmma::row_major> af;
            wmma::load_matrix_sync(af, As + (w * 16) * AP + kc * 16, AP);
#pragma unroll
            for (int nt = 0; nt < 4; nt++) {
                wmma::fragment<wmma::matrix_b, 16, 16, 16, __half, wmma::row_major> bf;
                wmma::load_matrix_sync(bf, Bs + (kc * 16) * AP + nt * 16, AP);
                wmma::mma_sync(acc[nt], af, bf, acc[nt]);
            }
        }
    }

    __syncthreads();   // done with As/Bs; reuse sbuf as Cs
    float* Cw = Cs + w * 16 * 68;
#pragma unroll
    for (int nt = 0; nt < 4; nt++)
        wmma::store_matrix_sync(Cw + nt * 16, acc[nt], 68, wmma::mem_row_major);
    __syncwarp();

    const float4* b4 = reinterpret_cast<const float4*>(bias);
    float4* out4 = reinterpret_cast<float4*>(out);
#pragma unroll
    for (int j = 0; j < 8; j++) {
        int idx = lane + j * 32;            // 16 rows x 16 float4
        int r = idx >> 4, c4 = idx & 15;
        int rho = rho0 + w * 16 + r;
        if (rho < 2 * V) {
            int v = rho >> 1, b = rho & 1;
            float4 cv = *reinterpret_cast<const float4*>(&Cw[r * 68 + c4 * 4]);
            float4 bb = __ldg(&b4[c4]);
            out4[(b * V + v) * 16 + c4] =
                make_float4(cv.x + bb.x, cv.y + bb.y, cv.z + bb.z, cv.w + bb.w);
        }
    }
}

// ---------------- launch ------------------------------------------------------
extern "C" void kernel_launch(void* const* d_in, const int* in_sizes, int n_in,
                              void* d_out, int out_size) {
    const float* inputs   = (const float*)d_in[0];   // [B, V, FIN]
    const float* weight   = (const float*)d_in[1];   // [K, FIN, FOUT]
    const float* bias     = (const float*)d_in[2];   // [FOUT]
    const float* lap_vals = (const float*)d_in[3];   // [E]
    const int*   lap_rows = (const int*)d_in[4];     // [E]
    const int*   lap_cols = (const int*)d_in[5];     // [E]
    float*       out      = (float*)d_out;           // [B, V, FOUT]

    front_kernel<<<TRANS_BLOCKS + HIST_BLOCKS + WCONV_BLOCKS, 256>>>(inputs, weight, lap_rows);
    scan_reduce_kernel<<<NB, 1024>>>();
    scan_write_kernel<<<NB, 1024>>>();
    scatter_kernel<<<HIST_BLOCKS, 256>>>(lap_vals, lap_rows, lap_cols);

    const int spmm_blocks = (V * 32 + 255) / 256;
    spmm_csr_kernel<<<spmm_blocks, 256>>>(0, 1, 0, 1.f, 0.f);    // x1 = L x0
    spmm_csr_kernel<<<spmm_blocks, 256>>>(1, 2, 0, 2.f, -1.f);   // x2 = 2Lx1 - x0
    spmm_csr_kernel<<<spmm_blocks, 256>>>(2, 3, 1, 2.f, -1.f);   // x3 = 2Lx2 - x1

    gemm_kernel<<<(2 * V + 127) / 128, 256>>>(bias, out);
}

// round 11
// speedup vs baseline: 1.0099x; 1.0099x over previous
#include <cuda_runtime.h>
#include <cuda_fp16.h>
#include <mma.h>

using namespace nvcuda;

#define V    50000
#define E    800000
#define BB   2
#define FIN  64
#define FOUT 64
#define KK   4
#define NB   ((V + 1023) / 1024)   // 49 scan blocks
#define FULLM 0xffffffffu

// ---------------- device scratch (allocation-free rule: __device__ globals) ----
// fp16 state. Per vertex v: 64 uints = 128 halves = 16 uint4;
//   uint j in [0,32): b=0, features (2j, 2j+1); j in [32,64): b=1.
__device__ unsigned g_H0[V * 64];
__device__ unsigned g_H1[V * 64];
__device__ unsigned g_H2[V * 64];
__device__ unsigned g_H3[V * 64];
__device__ unsigned g_Wh[KK * FIN * FOUT / 2];   // fp16 weights, 2 per uint
__device__ int      g_counts[V];     // zero-init; re-zeroed by scan_write
__device__ int      g_rowptr[V + 1];
__device__ int      g_bsums[NB];
__device__ int      g_rank[E];       // edge's within-row rank (from hist atomic)
__device__ int2     g_edge[E];       // (col, float-bits of val), row-sorted

__device__ __forceinline__ unsigned* hsel(int k) {
    switch (k) {
        case 0: return g_H0;
        case 1: return g_H1;
        case 2: return g_H2;
        default: return g_H3;
    }
}

// ---------------- 1) fused front: transpose+mirror + histogram(+rank) + W->fp16
#define TRANS_BLOCKS ((V * 32) / 256)            // 6250
#define HIST_BLOCKS  (E / 256)                   // 3125
#define WCONV_BLOCKS ((KK * FIN * FOUT / 2) / 256)   // 32
__global__ void front_kernel(const float* __restrict__ in,
                             const float* __restrict__ wt,
                             const int* __restrict__ rows) {
    int blk = blockIdx.x;
    if (blk < TRANS_BLOCKS) {
        int idx = blk * 256 + threadIdx.x;   // over V*32 f-pairs
        int v = idx >> 5;
        int fp = idx & 31;                   // features (2fp, 2fp+1)
        float2 a = __ldg(&reinterpret_cast<const float2*>(in)[v * 32 + fp]);          // b=0
        float2 c = __ldg(&reinterpret_cast<const float2*>(in)[V * 32 + v * 32 + fp]); // b=1
        __half2 h0 = __floats2half2_rn(a.x, a.y);
        __half2 h1 = __floats2half2_rn(c.x, c.y);
        g_H0[v * 64 + fp]      = *reinterpret_cast<unsigned*>(&h0);
        g_H0[v * 64 + 32 + fp] = *reinterpret_cast<unsigned*>(&h1);
    } else if (blk < TRANS_BLOCKS + HIST_BLOCKS) {
        int e = (blk - TRANS_BLOCKS) * 256 + threadIdx.x;
        int rr = __ldg(&rows[e]);
        g_rank[e] = atomicAdd(&g_counts[rr], 1);   // rank within row, for free
    } else {
        int i = (blk - TRANS_BLOCKS - HIST_BLOCKS) * 256 + threadIdx.x;  // over 8192
        __half2 h = __floats2half2_rn(wt[2 * i], wt[2 * i + 1]);
        g_Wh[i] = *reinterpret_cast<unsigned*>(&h);
    }
}

// ---------------- 2) CSR build ------------------------------------------------
__global__ void scan_reduce_kernel() {
    __shared__ int swarp[32];
    int tid = threadIdx.x;
    int i = blockIdx.x * 1024 + tid;
    int v = (i < V) ? g_counts[i] : 0;
    for (int o = 16; o > 0; o >>= 1) v += __shfl_down_sync(FULLM, v, o);
    if ((tid & 31) == 0) swarp[tid >> 5] = v;
    __syncthreads();
    if (tid < 32) {
        int s = swarp[tid];
        for (int o = 16; o > 0; o >>= 1) s += __shfl_down_sync(FULLM, s, o);
        if (tid == 0) g_bsums[blockIdx.x] = s;
    }
}

__global__ void scan_write_kernel() {
    __shared__ int s[1024];
    __shared__ int boff;
    int tid = threadIdx.x;
    if (tid == 0) {
        int run = 0;
        for (int j = 0; j < NB; j++) {
            if (j == (int)blockIdx.x) boff = run;
            run += g_bsums[j];
        }
        if (blockIdx.x == 0) g_rowptr[V] = run;   // == E
    }
    int i = blockIdx.x * 1024 + tid;
    int v = (i < V) ? g_counts[i] : 0;
    s[tid] = v;
    __syncthreads();
#pragma unroll
    for (int o = 1; o < 1024; o <<= 1) {
        int t = (tid >= o) ? s[tid - o] : 0;
        __syncthreads();
        s[tid] += t;
        __syncthreads();
    }
    if (i < V) {
        g_rowptr[i] = s[tid] - v + boff;
        g_counts[i] = 0;     // restore invariant for next replay
    }
}

// atomic-free scatter: p = rowptr[row] + rank[e]; pure load->store, full MLP
__global__ void scatter_kernel(const float* __restrict__ vals,
                               const int* __restrict__ rows,
                               const int* __restrict__ cols) {
    int e = blockIdx.x * blockDim.x + threadIdx.x;
    if (e >= E) return;
    int rr = __ldg(&rows[e]);
    int p  = __ldg(&g_rowptr[rr]) + g_rank[e];
    g_edge[p] = make_int2(__ldg(&cols[e]), __float_as_int(__ldg(&vals[e])));
}

// ---------------- 3) CSR SpMM (paired-edge LDG.128 gather) --------------------
// One warp per row; lane = 16*half + li. The two 16-lane halves process two
// DIFFERENT edges in the same LDG.128: half h gathers uint4 li of edge i+h's
// source row. 1 gather instruction per 2 edges; unroll x2 -> 4 edges in flight.
// Cross-half combine: 8x shfl_xor(16) once per row. Lane li owns features
// 8q..8q+7 of the 128-half row (q = li).
__device__ __forceinline__ void accum8(float* a, uint4 rr, float v) {
    float2 p0 = __half22float2(*reinterpret_cast<__half2*>(&rr.x));
    float2 p1 = __half22float2(*reinterpret_cast<__half2*>(&rr.y));
    float2 p2 = __half22float2(*reinterpret_cast<__half2*>(&rr.z));
    float2 p3 = __half22float2(*reinterpret_cast<__half2*>(&rr.w));
    a[0] = fmaf(v, p0.x, a[0]); a[1] = fmaf(v, p0.y, a[1]);
    a[2] = fmaf(v, p1.x, a[2]); a[3] = fmaf(v, p1.y, a[3]);
    a[4] = fmaf(v, p2.x, a[4]); a[5] = fmaf(v, p2.y, a[5]);
    a[6] = fmaf(v, p3.x, a[6]); a[7] = fmaf(v, p3.y, a[7]);
}

__global__ void spmm_csr_kernel(int ksrc, int kdst, int kprev,
                                float alpha, float beta) {
    int gtid = blockIdx.x * blockDim.x + threadIdx.x;
    int r = gtid >> 5;
    int lane = gtid & 31;
    if (r >= V) return;
    int half = lane >> 4;
    int li   = lane & 15;

    const uint4* __restrict__ hx = reinterpret_cast<const uint4*>(hsel(ksrc));
    int s = g_rowptr[r];
    int e = g_rowptr[r + 1];

    float acc0[8] = {0.f, 0.f, 0.f, 0.f, 0.f, 0.f, 0.f, 0.f};
    float acc1[8] = {0.f, 0.f, 0.f, 0.f, 0.f, 0.f, 0.f, 0.f};

    int i = s;
    for (; i + 4 <= e; i += 4) {
        int2 ea = __ldg(&g_edge[i + half]);          // 2 addrs/warp, broadcast
        int2 eb = __ldg(&g_edge[i + 2 + half]);
        uint4 ra = __ldg(&hx[ea.x * 16 + li]);       // 1 LDG.128 = 2 edges
        uint4 rb = __ldg(&hx[eb.x * 16 + li]);
        accum8(acc0, ra, __int_as_float(ea.y));
        accum8(acc1, rb, __int_as_float(eb.y));
    }
    for (; i < e; i += 2) {                          // remainder (warp-uniform)
        int idx = i + half;
        bool valid = idx < e;
        int2 ea = __ldg(&g_edge[valid ? idx : i]);   // safe addr when invalid
        float va = valid ? __int_as_float(ea.y) : 0.f;
        uint4 ra = __ldg(&hx[ea.x * 16 + li]);
        accum8(acc0, ra, va);
    }
#pragma unroll
    for (int q = 0; q < 8; q++) acc0[q] += acc1[q];
#pragma unroll
    for (int q = 0; q < 8; q++) acc0[q] += __shfl_xor_sync(FULLM, acc0[q], 16);

    if (half == 0) {
        float o[8];
        if (beta != 0.f) {
            uint4 rp = __ldg(&reinterpret_cast<const uint4*>(hsel(kprev))[r * 16 + li]);
            float2 p0 = __half22float2(*reinterpret_cast<__half2*>(&rp.x));
            float2 p1 = __half22float2(*reinterpret_cast<__half2*>(&rp.y));
            float2 p2 = __half22float2(*reinterpret_cast<__half2*>(&rp.z));
            float2 p3 = __half22float2(*reinterpret_cast<__half2*>(&rp.w));
            o[0] = fmaf(beta, p0.x, alpha * acc0[0]);
            o[1] = fmaf(beta, p0.y, alpha * acc0[1]);
            o[2] = fmaf(beta, p1.x, alpha * acc0[2]);
            o[3] = fmaf(beta, p1.y, alpha * acc0[3]);
            o[4] = fmaf(beta, p2.x, alpha * acc0[4]);
            o[5] = fmaf(beta, p2.y, alpha * acc0[5]);
            o[6] = fmaf(beta, p3.x, alpha * acc0[6]);
            o[7] = fmaf(beta, p3.y, alpha * acc0[7]);
        } else {
#pragma unroll
            for (int q = 0; q < 8; q++) o[q] = alpha * acc0[q];
        }
        uint4 m;
        __half2 m0 = __floats2half2_rn(o[0], o[1]);
        __half2 m1 = __floats2half2_rn(o[2], o[3]);
        __half2 m2 = __floats2half2_rn(o[4], o[5]);
        __half2 m3 = __floats2half2_rn(o[6], o[7]);
        m.x = *reinterpret_cast<unsigned*>(&m0);
        m.y = *reinterpret_cast<unsigned*>(&m1);
        m.z = *reinterpret_cast<unsigned*>(&m2);
        m.w = *reinterpret_cast<unsigned*>(&m3);
        reinterpret_cast<uint4*>(hsel(kdst))[r * 16 + li] = m;
    }
}

// ---------------- 4) tensor-core GEMM ----------------------------------------
#define AP 72   // padded half stride
__global__ void gemm_kernel(const float* __restrict__ bias,
                            float* __restrict__ out) {
    __shared__ __align__(16) char sbuf[35840];
    unsigned* As_u = reinterpret_cast<unsigned*>(sbuf);            // 128*36*4
    unsigned* Bs_u = reinterpret_cast<unsigned*>(sbuf + 18432);    //  64*36*4
    float*    Cs   = reinterpret_cast<float*>(sbuf);               // epilogue

    int tid = threadIdx.x;
    int w = tid >> 5;
    int lane = tid & 31;
    int rho0 = blockIdx.x * 128;

    wmma::fragment<wmma::accumulator, 16, 16, 16, float> acc[4];
#pragma unroll
    for (int nt = 0; nt < 4; nt++) wmma::fill_fragment(acc[nt], 0.f);

    for (int k = 0; k < KK; k++) {
        __syncthreads();
        const unsigned* m = hsel(k);
#pragma unroll
        for (int it = 0; it < 16; it++) {        // A: 128 rho-rows x 32 uints
            int i = tid + it * 256;
            int r = i >> 5, cu = i & 31;
            int rho = rho0 + r;
            unsigned val = 0u;
            if (rho < 2 * V)
                val = __ldcg(&m[(rho >> 1) * 64 + (rho & 1) * 32 + cu]);
            As_u[r * 36 + cu] = val;
        }
#pragma unroll
        for (int it = 0; it < 8; it++) {         // B: 64 f-rows x 32 uints
            int i = tid + it * 256;
            int f = i >> 5, cu = i & 31;
            Bs_u[f * 36 + cu] = __ldg(&g_Wh[(f * 4 + k) * 32 + cu]);
        }
        __syncthreads();

        const __half* As = reinterpret_cast<const __half*>(As_u);
        const __half* Bs = reinterpret_cast<const __half*>(Bs_u);
#pragma unroll
        for (int kc = 0; kc < 4; kc++) {
            wmma::fragment<wmma::matrix_a, 16, 16, 16, __half, wmma::row_major> af;
            wmma::load_matrix_sync(af, As + (w * 16) * AP + kc * 16, AP);
#pragma unroll
            for (int nt = 0; nt < 4; nt++) {
                wmma::fragment<wmma::matrix_b, 16, 16, 16, __half, wmma::row_major> bf;
                wmma::load_matrix_sync(bf, Bs + (kc * 16) * AP + nt * 16, AP);
                wmma::mma_sync(acc[nt], af, bf, acc[nt]);
            }
        }
    }

    __syncthreads();   // done with As/Bs; reuse sbuf as Cs
    float* Cw = Cs + w * 16 * 68;
#pragma unroll
    for (int nt = 0; nt < 4; nt++)
        wmma::store_matrix_sync(Cw + nt * 16, acc[nt], 68, wmma::mem_row_major);
    __syncwarp();

    const float4* b4 = reinterpret_cast<const float4*>(bias);
    float4* out4 = reinterpret_cast<float4*>(out);
#pragma unroll
    for (int j = 0; j < 8; j++) {
        int idx = lane + j * 32;            // 16 rows x 16 float4
        int r = idx >> 4, c4 = idx & 15;
        int rho = rho0 + w * 16 + r;
        if (rho < 2 * V) {
            int v = rho >> 1, b = rho & 1;
            float4 cv = *reinterpret_cast<const float4*>(&Cw[r * 68 + c4 * 4]);
            float4 bb = __ldg(&b4[c4]);
            out4[(b * V + v) * 16 + c4] =
                make_float4(cv.x + bb.x, cv.y + bb.y, cv.z + bb.z, cv.w + bb.w);
        }
    }
}

// ---------------- launch ------------------------------------------------------
extern "C" void kernel_launch(void* const* d_in, const int* in_sizes, int n_in,
                              void* d_out, int out_size) {
    const float* inputs   = (const float*)d_in[0];   // [B, V, FIN]
    const float* weight   = (const float*)d_in[1];   // [K, FIN, FOUT]
    const float* bias     = (const float*)d_in[2];   // [FOUT]
    const float* lap_vals = (const float*)d_in[3];   // [E]
    const int*   lap_rows = (const int*)d_in[4];     // [E]
    const int*   lap_cols = (const int*)d_in[5];     // [E]
    float*       out      = (float*)d_out;           // [B, V, FOUT]

    front_kernel<<<TRANS_BLOCKS + HIST_BLOCKS + WCONV_BLOCKS, 256>>>(inputs, weight, lap_rows);
    scan_reduce_kernel<<<NB, 1024>>>();
    scan_write_kernel<<<NB, 1024>>>();
    scatter_kernel<<<(E + 255) / 256, 256>>>(lap_vals, lap_rows, lap_cols);

    const int spmm_blocks = (V * 32 + 255) / 256;
    spmm_csr_kernel<<<spmm_blocks, 256>>>(0, 1, 0, 1.f, 0.f);    // x1 = L x0
    spmm_csr_kernel<<<spmm_blocks, 256>>>(1, 2, 0, 2.f, -1.f);   // x2 = 2Lx1 - x0
    spmm_csr_kernel<<<spmm_blocks, 256>>>(2, 3, 1, 2.f, -1.f);   // x3 = 2Lx2 - x1

    gemm_kernel<<<(2 * V + 127) / 128, 256>>>(bias, out);
}